// round 11
// baseline (speedup 1.0000x reference)
#include <cuda_runtime.h>

// Problem constants
#define BV   8
#define CV   19
#define HWv  (512 * 1024)              // 524288 = 2^19
#define NPIX (BV * HWv)                // 4194304
#define THREADS 256
#define PIX_PER_THREAD 4
#define NBLOCKS (NPIX / (THREADS * PIX_PER_THREAD))   // 4096

// Packed accumulator: bits [48..63] = arrived-block count, bits [0..47] =
// fixed-point loss sum (scale 2^22). One atomicAdd updates both fields, so
// the block observing count==NBLOCKS-1 in the returned old value knows the
// low bits hold every other block's partial. Fixed-point addition is
// associative -> bit-deterministic regardless of arrival order.
#define COUNT_ONE   (1ULL << 48)
#define VALUE_MASK  ((1ULL << 48) - 1)
#define SCALE       4194304.0          // 2^22

__device__ unsigned long long g_acc = 0ULL;   // reset by the winner each call

// minBlocksPerMultiprocessor=8 -> reg cap 32 -> 64 warps/SM (max). More
// concurrent warps = more outstanding sectors + better latency hiding for
// the exp/log gaps that currently leave DRAM idle ~20% of cycles.
__global__ void __launch_bounds__(THREADS, 8)
ce_fused_kernel(const float* __restrict__ logits,
                const int*   __restrict__ labels,
                float*       __restrict__ out) {
    const int tid  = blockIdx.x * THREADS + threadIdx.x;
    const int base = tid * PIX_PER_THREAD;          // first pixel of this thread
    const int b    = base >> 19;                    // image index (HW = 2^19)
    const int pix  = base & (HWv - 1);              // pixel within image

    const float4* lp =
        reinterpret_cast<const float4*>(logits + (size_t)b * CV * HWv + pix);
    const int4 lab = *reinterpret_cast<const int4*>(labels + base);

    float4 s  = make_float4(0.f, 0.f, 0.f, 0.f);
    float4 xl = make_float4(0.f, 0.f, 0.f, 0.f);

    #pragma unroll
    for (int c = 0; c < CV; ++c) {
        const float4 v = lp[c * (HWv / 4)];
        s.x += __expf(v.x);
        s.y += __expf(v.y);
        s.z += __expf(v.z);
        s.w += __expf(v.w);
        if (c == lab.x) xl.x = v.x;
        if (c == lab.y) xl.y = v.y;
        if (c == lab.z) xl.z = v.z;
        if (c == lab.w) xl.w = v.w;
    }

    // nll = log(sum exp) - x_label ; zero at ignored pixels (label < 0)
    float loss = 0.f;
    loss += (lab.x >= 0) ? (__logf(s.x) - xl.x) : 0.f;
    loss += (lab.y >= 0) ? (__logf(s.y) - xl.y) : 0.f;
    loss += (lab.z >= 0) ? (__logf(s.z) - xl.z) : 0.f;
    loss += (lab.w >= 0) ? (__logf(s.w) - xl.w) : 0.f;

    // warp reduce
    #pragma unroll
    for (int o = 16; o > 0; o >>= 1)
        loss += __shfl_down_sync(0xFFFFFFFFu, loss, o);

    __shared__ float ws[THREADS / 32];
    if ((threadIdx.x & 31) == 0) ws[threadIdx.x >> 5] = loss;
    __syncthreads();

    if (threadIdx.x == 0) {
        float t = 0.f;
        #pragma unroll
        for (int w = 0; w < THREADS / 32; ++w) t += ws[w];

        const unsigned long long q =
            (unsigned long long)((double)t * SCALE);

        const unsigned long long old = atomicAdd(&g_acc, COUNT_ONE + q);

        if ((old >> 48) == (unsigned long long)(NBLOCKS - 1)) {
            const unsigned long long total = (old & VALUE_MASK) + q;
            out[0] = (float)((double)total * (1.0 / (SCALE * (double)NPIX)));
            g_acc = 0ULL;   // reset for the next graph replay
        }
    }
}

extern "C" void kernel_launch(void* const* d_in, const int* in_sizes, int n_in,
                              void* d_out, int out_size) {
    const float* logits = (const float*)d_in[0];
    const int*   labels = (const int*)d_in[1];
    // d_in[2] (smooth_labels) is dead in the reference forward — never read.
    float* out = (float*)d_out;

    ce_fused_kernel<<<NBLOCKS, THREADS>>>(logits, labels, out);
}

// round 12
// speedup vs baseline: 1.0466x; 1.0466x over previous
#include <cuda_runtime.h>

// Problem constants
#define BV   8
#define CV   19
#define HWv  (512 * 1024)              // 524288 = 2^19
#define NPIX (BV * HWv)                // 4194304
#define THREADS 128
#define PIX_PER_THREAD 4
#define NBLOCKS (NPIX / (THREADS * PIX_PER_THREAD))   // 8192

// Packed accumulator: bits [48..63] = arrived-block count, bits [0..47] =
// fixed-point loss sum (scale 2^22). One atomicAdd updates both fields, so
// the block observing count==NBLOCKS-1 in the returned old value knows the
// low bits hold every other block's partial. Fixed-point addition is
// associative -> bit-deterministic regardless of arrival order.
// Max sum ~1.4e7 * 2^22 = 5.9e13 < 2^48; count 8192 < 2^16.
#define COUNT_ONE   (1ULL << 48)
#define VALUE_MASK  ((1ULL << 48) - 1)
#define SCALE       4194304.0          // 2^22

__device__ unsigned long long g_acc = 0ULL;   // reset by the winner each call

__global__ __launch_bounds__(THREADS)
void ce_fused_kernel(const float* __restrict__ logits,
                     const int*   __restrict__ labels,
                     float*       __restrict__ out) {
    const int tid  = blockIdx.x * THREADS + threadIdx.x;
    const int base = tid * PIX_PER_THREAD;          // first pixel of this thread
    const int b    = base >> 19;                    // image index (HW = 2^19)
    const int pix  = base & (HWv - 1);              // pixel within image

    const float4* lp =
        reinterpret_cast<const float4*>(logits + (size_t)b * CV * HWv + pix);
    const int4 lab = *reinterpret_cast<const int4*>(labels + base);

    float4 s  = make_float4(0.f, 0.f, 0.f, 0.f);
    float4 xl = make_float4(0.f, 0.f, 0.f, 0.f);

    #pragma unroll
    for (int c = 0; c < CV; ++c) {
        const float4 v = lp[c * (HWv / 4)];
        s.x += __expf(v.x);
        s.y += __expf(v.y);
        s.z += __expf(v.z);
        s.w += __expf(v.w);
        if (c == lab.x) xl.x = v.x;
        if (c == lab.y) xl.y = v.y;
        if (c == lab.z) xl.z = v.z;
        if (c == lab.w) xl.w = v.w;
    }

    // nll = log(sum exp) - x_label ; zero at ignored pixels (label < 0)
    float loss = 0.f;
    loss += (lab.x >= 0) ? (__logf(s.x) - xl.x) : 0.f;
    loss += (lab.y >= 0) ? (__logf(s.y) - xl.y) : 0.f;
    loss += (lab.z >= 0) ? (__logf(s.z) - xl.z) : 0.f;
    loss += (lab.w >= 0) ? (__logf(s.w) - xl.w) : 0.f;

    // warp reduce
    #pragma unroll
    for (int o = 16; o > 0; o >>= 1)
        loss += __shfl_down_sync(0xFFFFFFFFu, loss, o);

    __shared__ float ws[THREADS / 32];
    if ((threadIdx.x & 31) == 0) ws[threadIdx.x >> 5] = loss;
    __syncthreads();

    if (threadIdx.x == 0) {
        float t = 0.f;
        #pragma unroll
        for (int w = 0; w < THREADS / 32; ++w) t += ws[w];

        const unsigned long long q =
            (unsigned long long)((double)t * SCALE);

        const unsigned long long old = atomicAdd(&g_acc, COUNT_ONE + q);

        if ((old >> 48) == (unsigned long long)(NBLOCKS - 1)) {
            const unsigned long long total = (old & VALUE_MASK) + q;
            out[0] = (float)((double)total * (1.0 / (SCALE * (double)NPIX)));
            g_acc = 0ULL;   // reset for the next graph replay
        }
    }
}

extern "C" void kernel_launch(void* const* d_in, const int* in_sizes, int n_in,
                              void* d_out, int out_size) {
    const float* logits = (const float*)d_in[0];
    const int*   labels = (const int*)d_in[1];
    // d_in[2] (smooth_labels) is dead in the reference forward — never read.
    float* out = (float*)d_out;

    ce_fused_kernel<<<NBLOCKS, THREADS>>>(logits, labels, out);
}